// round 1
// baseline (speedup 1.0000x reference)
#include <cuda_runtime.h>

// AdaptiveFilter: per-pixel learned bilateral filter.
// x, guidance: (B=2, C=3, H=512, W=512) float32
// w0: (B, H*W, 4, 4) float32 half-kernel logits; full 7x7 kernel via reflect
// out: (B, C, H, W) float32
//
// out_c(p) = sum_k x_c(p+dk) * e_k / sum_k e_k,
//   e_k = exp(w_k - 50 * (sum_c |g_c(p+dk) - g_c(p)|)^2)
// (softmax normalizer cancels in the ratio.)

namespace {
constexpr int B = 2, C = 3, H = 512, W = 512;
constexpr int TS = 16;           // pixel tile side
constexpr int HALO = 3;          // 7x7 kernel radius
constexpr int TILE = TS + 2 * HALO;  // 22
}

__global__ __launch_bounds__(TS * TS)
void adaptive_filter_kernel(const float* __restrict__ x,
                            const float* __restrict__ g,
                            const float* __restrict__ w0,
                            float* __restrict__ out) {
    // Packed shared tiles: sgx = (g0,g1,g2,x0), sx2 = (x1,x2). +1 pad col.
    __shared__ float4 sgx[TILE][TILE + 1];
    __shared__ float2 sx2[TILE][TILE + 1];

    const int b  = blockIdx.z;
    const int h0 = blockIdx.y * TS;
    const int w0c = blockIdx.x * TS;
    const int tid = threadIdx.y * TS + threadIdx.x;

    const float* __restrict__ gb = g + (size_t)b * C * H * W;
    const float* __restrict__ xb = x + (size_t)b * C * H * W;

    // Cooperative halo load with reflect padding (single reflection suffices:
    // pad=3 << 512).
    for (int idx = tid; idx < TILE * TILE; idx += TS * TS) {
        const int ty = idx / TILE;
        const int tx = idx - ty * TILE;
        int gy = h0 + ty - HALO;
        gy = gy < 0 ? -gy : (gy >= H ? 2 * H - 2 - gy : gy);
        int gx = w0c + tx - HALO;
        gx = gx < 0 ? -gx : (gx >= W ? 2 * W - 2 - gx : gx);
        const int p = gy * W + gx;
        const float g0 = gb[p];
        const float g1 = gb[H * W + p];
        const float g2 = gb[2 * H * W + p];
        const float x0 = xb[p];
        const float x1 = xb[H * W + p];
        const float x2 = xb[2 * H * W + p];
        sgx[ty][tx] = make_float4(g0, g1, g2, x0);
        sx2[ty][tx] = make_float2(x1, x2);
    }

    // Per-pixel half-kernel logits: 16 contiguous floats.
    const int h = h0 + threadIdx.y;
    const int w = w0c + threadIdx.x;
    const float4* __restrict__ wp =
        reinterpret_cast<const float4*>(w0 + ((size_t)b * H * W + (size_t)h * W + w) * 16);
    const float4 wa = wp[0];
    const float4 wbv = wp[1];
    const float4 wc = wp[2];
    const float4 wd = wp[3];
    const float wk[16] = {wa.x, wa.y, wa.z, wa.w,
                          wbv.x, wbv.y, wbv.z, wbv.w,
                          wc.x, wc.y, wc.z, wc.w,
                          wd.x, wd.y, wd.z, wd.w};

    __syncthreads();

    const float4 gc = sgx[threadIdx.y + HALO][threadIdx.x + HALO];

    float n0 = 0.f, n1 = 0.f, n2 = 0.f, den = 0.f;

#pragma unroll
    for (int i = 0; i < 7; ++i) {
        const int hi = i < 4 ? i : 6 - i;  // reflect of half-kernel rows
#pragma unroll
        for (int j = 0; j < 7; ++j) {
            const int hj = j < 4 ? j : 6 - j;
            const float4 v  = sgx[threadIdx.y + i][threadIdx.x + j];
            const float2 v2 = sx2[threadIdx.y + i][threadIdx.x + j];
            const float d = fabsf(v.x - gc.x) + fabsf(v.y - gc.y) + fabsf(v.z - gc.z);
            const float e = __expf(fmaf(-50.0f * d, d, wk[hi * 4 + hj]));
            n0 = fmaf(v.w, e, n0);
            n1 = fmaf(v2.x, e, n1);
            n2 = fmaf(v2.y, e, n2);
            den += e;
        }
    }

    const float inv = __fdividef(1.0f, den);
    const size_t o = ((size_t)b * C * H + (size_t)h) * W + w;
    out[o] = n0 * inv;
    out[o + (size_t)H * W] = n1 * inv;
    out[o + (size_t)2 * H * W] = n2 * inv;
}

extern "C" void kernel_launch(void* const* d_in, const int* in_sizes, int n_in,
                              void* d_out, int out_size) {
    const float* x  = (const float*)d_in[0];
    const float* g  = (const float*)d_in[1];
    const float* w0 = (const float*)d_in[2];
    float* out = (float*)d_out;

    dim3 block(TS, TS);
    dim3 grid(W / TS, H / TS, B);
    adaptive_filter_kernel<<<grid, block>>>(x, g, w0, out);
}